// round 14
// baseline (speedup 1.0000x reference)
#include <cuda_runtime.h>

#define B_ 256
#define S_ 196
#define R_ 1024
#define H_ 512

#define KSPLIT 8
#define KCHUNK (R_ / KSPLIT)     // 128

// GEMM tiling for k_h2att
#define BM 64
#define BN 64
#define BK 16
#define NTILES (KCHUNK / BK)     // 8

#define BCHUNK (B_ / 2)          // 128 rows per pipeline chunk

// Scratch (no allocations allowed anywhere)
__device__ float g_att_h_part[KSPLIT * B_ * H_];
__device__ float g_scores[B_ * S_];

__device__ __forceinline__ float tanh_fast(float x) {
    float y;
    asm("tanh.approx.f32 %0, %1;" : "=f"(y) : "f"(x));
    return y;
}

// ---------------------------------------------------------------------------
// Kernel A: partial att_h = hidden @ W^T (+bias on z==0 split), one B-chunk.
// grid (H/BN=8, BCHUNK/BM=2, KSPLIT=8), 256 threads, 4x4 micro-tile,
// ping-pong smem + register staging (one sync per k-tile).
// ---------------------------------------------------------------------------
__global__ void __launch_bounds__(256)
k_h2att(const float* __restrict__ hidden,
        const float* __restrict__ W,
        const float* __restrict__ bias,
        int boff) {
    __shared__ __align__(16) float As[2][BK][BM + 4];   // [buf][kk][b-row]
    __shared__ __align__(16) float Bs[2][BK][BN + 4];   // [buf][kk][h-col]
    const int h0 = blockIdx.x * BN;
    const int b0 = boff + blockIdx.y * BM;
    const int z  = blockIdx.z;
    const int tid = threadIdx.x;

    const int lrow = tid >> 2;            // 0..63 (row to stage)
    const int lk   = (tid & 3) * 4;       // 0,4,8,12 (k quad)

    const int tx4 = (tid & 15) * 4;       // h micro col
    const int ty4 = (tid >> 4) * 4;       // b micro row

    float acc[4][4] = {};

    const int kbeg = z * KCHUNK;
    const float* ha = &hidden[(size_t)(b0 + lrow) * R_ + kbeg + lk];
    const float* wa = &W[(size_t)(h0 + lrow) * R_ + kbeg + lk];

    {
        float4 av = *(const float4*)ha;
        float4 bv = *(const float4*)wa;
        As[0][lk + 0][lrow] = av.x;
        As[0][lk + 1][lrow] = av.y;
        As[0][lk + 2][lrow] = av.z;
        As[0][lk + 3][lrow] = av.w;
        Bs[0][lk + 0][lrow] = bv.x;
        Bs[0][lk + 1][lrow] = bv.y;
        Bs[0][lk + 2][lrow] = bv.z;
        Bs[0][lk + 3][lrow] = bv.w;
    }
    __syncthreads();

    #pragma unroll
    for (int i = 0; i < NTILES; i++) {
        float4 av, bv;
        if (i + 1 < NTILES) {              // issue next tile's loads early
            av = *(const float4*)(ha + (i + 1) * BK);
            bv = *(const float4*)(wa + (i + 1) * BK);
        }

        const int p = i & 1;
        #pragma unroll
        for (int kk = 0; kk < BK; kk++) {
            float4 a = *(const float4*)&As[p][kk][ty4];
            float4 b = *(const float4*)&Bs[p][kk][tx4];
            acc[0][0] = fmaf(a.x, b.x, acc[0][0]);
            acc[0][1] = fmaf(a.x, b.y, acc[0][1]);
            acc[0][2] = fmaf(a.x, b.z, acc[0][2]);
            acc[0][3] = fmaf(a.x, b.w, acc[0][3]);
            acc[1][0] = fmaf(a.y, b.x, acc[1][0]);
            acc[1][1] = fmaf(a.y, b.y, acc[1][1]);
            acc[1][2] = fmaf(a.y, b.z, acc[1][2]);
            acc[1][3] = fmaf(a.y, b.w, acc[1][3]);
            acc[2][0] = fmaf(a.z, b.x, acc[2][0]);
            acc[2][1] = fmaf(a.z, b.y, acc[2][1]);
            acc[2][2] = fmaf(a.z, b.z, acc[2][2]);
            acc[2][3] = fmaf(a.z, b.w, acc[2][3]);
            acc[3][0] = fmaf(a.w, b.x, acc[3][0]);
            acc[3][1] = fmaf(a.w, b.y, acc[3][1]);
            acc[3][2] = fmaf(a.w, b.z, acc[3][2]);
            acc[3][3] = fmaf(a.w, b.w, acc[3][3]);
        }

        if (i + 1 < NTILES) {
            const int q = (i + 1) & 1;
            As[q][lk + 0][lrow] = av.x;
            As[q][lk + 1][lrow] = av.y;
            As[q][lk + 2][lrow] = av.z;
            As[q][lk + 3][lrow] = av.w;
            Bs[q][lk + 0][lrow] = bv.x;
            Bs[q][lk + 1][lrow] = bv.y;
            Bs[q][lk + 2][lrow] = bv.z;
            Bs[q][lk + 3][lrow] = bv.w;
            __syncthreads();
        }
    }

    float4 bias4 = make_float4(0.f, 0.f, 0.f, 0.f);
    if (z == 0) bias4 = *(const float4*)&bias[h0 + tx4];

    float* outp = g_att_h_part + (size_t)z * B_ * H_;
    #pragma unroll
    for (int i = 0; i < 4; i++) {
        float4 r = make_float4(acc[i][0] + bias4.x,
                               acc[i][1] + bias4.y,
                               acc[i][2] + bias4.z,
                               acc[i][3] + bias4.w);
        *(float4*)&outp[(size_t)(b0 + ty4 + i) * H_ + h0 + tx4] = r;
    }
}

// ---------------------------------------------------------------------------
// Kernel B: scores for one B-chunk. grid (2, BCHUNK), 512 threads.
// ---------------------------------------------------------------------------
__global__ void __launch_bounds__(512)
k_scores(const float* __restrict__ p_att,
         const float* __restrict__ in_w,
         const float* __restrict__ alpha_w,
         const float* __restrict__ alpha_b,
         int boff) {
    __shared__ __align__(16) float sh_ah[H_];
    __shared__ __align__(16) float sh_al[H_];
    const int b = boff + blockIdx.y;
    const int c = blockIdx.x;          // 0 or 1 (half of S)
    const int tid = threadIdx.x;

    if (tid < H_) {
        size_t o = (size_t)b * H_ + tid;
        float v = 0.f;
        #pragma unroll
        for (int p = 0; p < KSPLIT; p++)
            v += g_att_h_part[(size_t)p * B_ * H_ + o];
        sh_ah[tid] = v;
        sh_al[tid] = alpha_w[tid];
    }
    __syncthreads();

    const int warp = tid >> 5, lane = tid & 31;
    const float4* ah4 = (const float4*)sh_ah;
    const float4* al4 = (const float4*)sh_al;
    const float ab0 = alpha_b[0];

    for (int sl = warp; sl < S_ / 2; sl += 16) {
        const int s = c * (S_ / 2) + sl;
        const float iw = in_w[b * S_ + s];
        const float4* p4 = (const float4*)(p_att + ((size_t)b * S_ + s) * H_);
        float acc = 0.f;
        #pragma unroll
        for (int j = 0; j < 4; j++) {
            float4 p = p4[j * 32 + lane];
            float4 a = ah4[j * 32 + lane];
            float4 w = al4[j * 32 + lane];
            acc += tanh_fast(fmaf(iw, p.x, a.x)) * w.x;
            acc += tanh_fast(fmaf(iw, p.y, a.y)) * w.y;
            acc += tanh_fast(fmaf(iw, p.z, a.z)) * w.z;
            acc += tanh_fast(fmaf(iw, p.w, a.w)) * w.w;
        }
        #pragma unroll
        for (int o = 16; o; o >>= 1)
            acc += __shfl_xor_sync(0xffffffffu, acc, o);
        if (lane == 0)
            g_scores[b * S_ + s] = acc + ab0;
    }
}

// ---------------------------------------------------------------------------
// Kernel C: fused softmax + direct pooling for one B-chunk. grid (4, BCHUNK),
// 256 threads. Softmax recomputed per block (deterministic, identical order);
// rc==0 writes weight. Each thread owns one scalar r column over all 196 s.
// ---------------------------------------------------------------------------
__global__ void __launch_bounds__(256)
k_pool(const float* __restrict__ att_feats,
       float* __restrict__ weight_out,
       float* __restrict__ att_res,
       int boff) {
    __shared__ float ws[S_];
    __shared__ float red[8];
    const int b  = boff + blockIdx.y;
    const int rc = blockIdx.x;         // r chunk 0..3
    const int tid = threadIdx.x;
    const int warp = tid >> 5, lane = tid & 31;

    // --- softmax over S (256 threads, one score each) ---
    float v = (tid < S_) ? g_scores[b * S_ + tid] : -1e30f;
    float m = v;
    #pragma unroll
    for (int o = 16; o; o >>= 1) m = fmaxf(m, __shfl_xor_sync(0xffffffffu, m, o));
    if (lane == 0) red[warp] = m;
    __syncthreads();
    if (tid == 0) {
        float mm = red[0];
        #pragma unroll
        for (int i = 1; i < 8; i++) mm = fmaxf(mm, red[i]);
        red[0] = mm;
    }
    __syncthreads();
    m = red[0];
    __syncthreads();

    float e = (tid < S_) ? __expf(v - m) : 0.f;
    float su = e;
    #pragma unroll
    for (int o = 16; o; o >>= 1) su += __shfl_xor_sync(0xffffffffu, su, o);
    if (lane == 0) red[warp] = su;
    __syncthreads();
    if (tid == 0) {
        float ss = 0.f;
        #pragma unroll
        for (int i = 0; i < 8; i++) ss += red[i];
        red[0] = ss;
    }
    __syncthreads();
    const float inv = 1.0f / red[0];
    if (tid < S_) {
        float wnorm = e * inv;
        ws[tid] = wnorm;
        if (rc == 0) weight_out[b * S_ + tid] = wnorm;
    }
    __syncthreads();

    // --- direct pooling: this thread's r column, all 196 s ---
    const int r = rc * 256 + tid;
    const float* af = att_feats + (size_t)b * S_ * R_ + r;
    float acc = 0.f;
    #pragma unroll 7
    for (int s = 0; s < S_; s++) {
        acc = fmaf(ws[s], af[(size_t)s * R_], acc);
    }
    att_res[(size_t)b * R_ + r] = acc;
}

// ---------------------------------------------------------------------------
// Two-chunk software pipeline across a forked stream.
//   L : A(c0) -ev-> A(c1) -> B(c1) -> C(c1) -> wait(join)
//   s1:        \--> B(c0) -> C(c0) -> record(join)
// ---------------------------------------------------------------------------
static cudaStream_t g_s1 = nullptr;
static cudaEvent_t  g_evA0 = nullptr, g_evJoin = nullptr;

extern "C" void kernel_launch(void* const* d_in, const int* in_sizes, int n_in,
                              void* d_out, int out_size) {
    const float* att_feats = (const float*)d_in[0];  // [B,S,R]
    const float* p_att     = (const float*)d_in[1];  // [B,S,H]
    const float* hidden    = (const float*)d_in[2];  // [B,R]
    const float* in_w      = (const float*)d_in[3];  // [B,S]
    const float* h2w       = (const float*)d_in[4];  // [H,R]
    const float* h2b       = (const float*)d_in[5];  // [H]
    const float* aw        = (const float*)d_in[6];  // [1,H]
    const float* ab        = (const float*)d_in[7];  // [1]

    float* out     = (float*)d_out;
    float* att_res = out;                 // [B,R]
    float* weight  = out + B_ * R_;       // [B,S]

    if (g_s1 == nullptr) {
        cudaStreamCreateWithFlags(&g_s1, cudaStreamNonBlocking);
        cudaEventCreateWithFlags(&g_evA0, cudaEventDisableTiming);
        cudaEventCreateWithFlags(&g_evJoin, cudaEventDisableTiming);
    }

    const dim3 gA(H_ / BN, BCHUNK / BM, KSPLIT);
    const dim3 gB(2, BCHUNK);
    const dim3 gC(4, BCHUNK);

    // chunk 0 GEMM on the main stream, then fork
    k_h2att<<<gA, 256>>>(hidden, h2w, h2b, 0);
    cudaEventRecord(g_evA0, 0);

    // main stream continues with chunk 1
    k_h2att <<<gA, 256>>>(hidden, h2w, h2b, BCHUNK);
    k_scores<<<gB, 512>>>(p_att, in_w, aw, ab, BCHUNK);
    k_pool  <<<gC, 256>>>(att_feats, weight, att_res, BCHUNK);

    // forked stream handles chunk 0's BW-bound tail
    cudaStreamWaitEvent(g_s1, g_evA0, 0);
    k_scores<<<gB, 512, 0, g_s1>>>(p_att, in_w, aw, ab, 0);
    k_pool  <<<gC, 256, 0, g_s1>>>(att_feats, weight, att_res, 0);
    cudaEventRecord(g_evJoin, g_s1);

    // join back to the captured stream
    cudaStreamWaitEvent(0, g_evJoin, 0);
}

// round 15
// speedup vs baseline: 1.0868x; 1.0868x over previous
#include <cuda_runtime.h>

#define B_ 256
#define S_ 196
#define R_ 1024
#define H_ 512

#define KSPLIT 16
#define KCHUNK (R_ / KSPLIT)     // 64

// GEMM tiling for k_h2att
#define BM 64
#define BN 64
#define BK 16
#define NTILES (KCHUNK / BK)     // 4

// Scratch (no allocations allowed anywhere)
__device__ float g_att_h_part[KSPLIT * B_ * H_];
__device__ float g_scores[B_ * S_];

__device__ __forceinline__ float tanh_fast(float x) {
    float y;
    asm("tanh.approx.f32 %0, %1;" : "=f"(y) : "f"(x));
    return y;
}

// ---------------------------------------------------------------------------
// Kernel A: partial att_h = hidden @ W^T (+bias on z==0 split).
// grid (8, 4, KSPLIT=16) = 512 blocks, 256 threads, 4x4 micro-tile,
// ping-pong smem + register staging. Triggers PDL for the consumer.
// ---------------------------------------------------------------------------
__global__ void __launch_bounds__(256)
k_h2att(const float* __restrict__ hidden,
        const float* __restrict__ W,
        const float* __restrict__ bias) {
    __shared__ __align__(16) float As[2][BK][BM + 4];   // [buf][kk][b-row]
    __shared__ __align__(16) float Bs[2][BK][BN + 4];   // [buf][kk][h-col]
    const int h0 = blockIdx.x * BN;
    const int b0 = blockIdx.y * BM;
    const int z  = blockIdx.z;
    const int tid = threadIdx.x;

    const int lrow = tid >> 2;            // 0..63 (row to stage)
    const int lk   = (tid & 3) * 4;       // 0,4,8,12 (k quad)

    const int tx4 = (tid & 15) * 4;       // h micro col
    const int ty4 = (tid >> 4) * 4;       // b micro row

    float acc[4][4] = {};

    const int kbeg = z * KCHUNK;
    const float* ha = &hidden[(size_t)(b0 + lrow) * R_ + kbeg + lk];
    const float* wa = &W[(size_t)(h0 + lrow) * R_ + kbeg + lk];

    {
        float4 av = *(const float4*)ha;
        float4 bv = *(const float4*)wa;
        As[0][lk + 0][lrow] = av.x;
        As[0][lk + 1][lrow] = av.y;
        As[0][lk + 2][lrow] = av.z;
        As[0][lk + 3][lrow] = av.w;
        Bs[0][lk + 0][lrow] = bv.x;
        Bs[0][lk + 1][lrow] = bv.y;
        Bs[0][lk + 2][lrow] = bv.z;
        Bs[0][lk + 3][lrow] = bv.w;
    }
    __syncthreads();

    #pragma unroll
    for (int i = 0; i < NTILES; i++) {
        float4 av, bv;
        if (i + 1 < NTILES) {              // issue next tile's loads early
            av = *(const float4*)(ha + (i + 1) * BK);
            bv = *(const float4*)(wa + (i + 1) * BK);
        }

        const int p = i & 1;
        #pragma unroll
        for (int kk = 0; kk < BK; kk++) {
            float4 a = *(const float4*)&As[p][kk][ty4];
            float4 b = *(const float4*)&Bs[p][kk][tx4];
            acc[0][0] = fmaf(a.x, b.x, acc[0][0]);
            acc[0][1] = fmaf(a.x, b.y, acc[0][1]);
            acc[0][2] = fmaf(a.x, b.z, acc[0][2]);
            acc[0][3] = fmaf(a.x, b.w, acc[0][3]);
            acc[1][0] = fmaf(a.y, b.x, acc[1][0]);
            acc[1][1] = fmaf(a.y, b.y, acc[1][1]);
            acc[1][2] = fmaf(a.y, b.z, acc[1][2]);
            acc[1][3] = fmaf(a.y, b.w, acc[1][3]);
            acc[2][0] = fmaf(a.z, b.x, acc[2][0]);
            acc[2][1] = fmaf(a.z, b.y, acc[2][1]);
            acc[2][2] = fmaf(a.z, b.z, acc[2][2]);
            acc[2][3] = fmaf(a.z, b.w, acc[2][3]);
            acc[3][0] = fmaf(a.w, b.x, acc[3][0]);
            acc[3][1] = fmaf(a.w, b.y, acc[3][1]);
            acc[3][2] = fmaf(a.w, b.z, acc[3][2]);
            acc[3][3] = fmaf(a.w, b.w, acc[3][3]);
        }

        if (i + 1 < NTILES) {
            const int q = (i + 1) & 1;
            As[q][lk + 0][lrow] = av.x;
            As[q][lk + 1][lrow] = av.y;
            As[q][lk + 2][lrow] = av.z;
            As[q][lk + 3][lrow] = av.w;
            Bs[q][lk + 0][lrow] = bv.x;
            Bs[q][lk + 1][lrow] = bv.y;
            Bs[q][lk + 2][lrow] = bv.z;
            Bs[q][lk + 3][lrow] = bv.w;
            __syncthreads();
        }
    }

    float4 bias4 = make_float4(0.f, 0.f, 0.f, 0.f);
    if (z == 0) bias4 = *(const float4*)&bias[h0 + tx4];

    float* outp = g_att_h_part + (size_t)z * B_ * H_;
    #pragma unroll
    for (int i = 0; i < 4; i++) {
        float4 r = make_float4(acc[i][0] + bias4.x,
                               acc[i][1] + bias4.y,
                               acc[i][2] + bias4.z,
                               acc[i][3] + bias4.w);
        *(float4*)&outp[(size_t)(b0 + ty4 + i) * H_ + h0 + tx4] = r;
    }

#if __CUDA_ARCH__ >= 900
    cudaTriggerProgrammaticLaunchCompletion();
#endif
}

// ---------------------------------------------------------------------------
// Kernel B: scores. grid (2, B), 512 threads (16 warps). PDL consumer:
// preamble loads alpha/in_w (independent), then grid-dep-sync, then att_h.
// ---------------------------------------------------------------------------
__global__ void __launch_bounds__(512)
k_scores(const float* __restrict__ p_att,
         const float* __restrict__ in_w,
         const float* __restrict__ alpha_w,
         const float* __restrict__ alpha_b) {
    __shared__ __align__(16) float sh_ah[H_];
    __shared__ __align__(16) float sh_al[H_];
    __shared__ float sh_iw[S_ / 2];
    const int b = blockIdx.y;
    const int c = blockIdx.x;          // 0 or 1 (half of S)
    const int tid = threadIdx.x;

    // ---- independent preamble (runs under PDL overlap) ----
    if (tid < H_) sh_al[tid] = alpha_w[tid];
    if (tid < S_ / 2) sh_iw[tid] = in_w[b * S_ + c * (S_ / 2) + tid];
    const float ab0 = alpha_b[0];

#if __CUDA_ARCH__ >= 900
    cudaGridDependencySynchronize();
#endif

    if (tid < H_) {
        size_t o = (size_t)b * H_ + tid;
        float v = 0.f;
        #pragma unroll
        for (int p = 0; p < KSPLIT; p++)
            v += g_att_h_part[(size_t)p * B_ * H_ + o];
        sh_ah[tid] = v;
    }
    __syncthreads();

    const int warp = tid >> 5, lane = tid & 31;
    const float4* ah4 = (const float4*)sh_ah;
    const float4* al4 = (const float4*)sh_al;

    for (int sl = warp; sl < S_ / 2; sl += 16) {
        const int s = c * (S_ / 2) + sl;
        const float iw = sh_iw[sl];
        const float4* p4 = (const float4*)(p_att + ((size_t)b * S_ + s) * H_);
        float acc = 0.f;
        #pragma unroll
        for (int j = 0; j < 4; j++) {
            float4 p = p4[j * 32 + lane];
            float4 a = ah4[j * 32 + lane];
            float4 w = al4[j * 32 + lane];
            acc += tanh_fast(fmaf(iw, p.x, a.x)) * w.x;
            acc += tanh_fast(fmaf(iw, p.y, a.y)) * w.y;
            acc += tanh_fast(fmaf(iw, p.z, a.z)) * w.z;
            acc += tanh_fast(fmaf(iw, p.w, a.w)) * w.w;
        }
        #pragma unroll
        for (int o = 16; o; o >>= 1)
            acc += __shfl_xor_sync(0xffffffffu, acc, o);
        if (lane == 0)
            g_scores[b * S_ + s] = acc + ab0;
    }

#if __CUDA_ARCH__ >= 900
    cudaTriggerProgrammaticLaunchCompletion();
#endif
}

// ---------------------------------------------------------------------------
// Kernel C: fused softmax + direct pooling. grid (4, B), 256 threads.
// PDL consumer: syncs on scores before reading g_scores.
// ---------------------------------------------------------------------------
__global__ void __launch_bounds__(256)
k_pool(const float* __restrict__ att_feats,
       float* __restrict__ weight_out,
       float* __restrict__ att_res) {
    __shared__ float ws[S_];
    __shared__ float red[8];
    const int b  = blockIdx.y;
    const int rc = blockIdx.x;         // r chunk 0..3
    const int tid = threadIdx.x;
    const int warp = tid >> 5, lane = tid & 31;

#if __CUDA_ARCH__ >= 900
    cudaGridDependencySynchronize();
#endif

    // --- softmax over S (256 threads, one score each) ---
    float v = (tid < S_) ? g_scores[b * S_ + tid] : -1e30f;
    float m = v;
    #pragma unroll
    for (int o = 16; o; o >>= 1) m = fmaxf(m, __shfl_xor_sync(0xffffffffu, m, o));
    if (lane == 0) red[warp] = m;
    __syncthreads();
    if (tid == 0) {
        float mm = red[0];
        #pragma unroll
        for (int i = 1; i < 8; i++) mm = fmaxf(mm, red[i]);
        red[0] = mm;
    }
    __syncthreads();
    m = red[0];
    __syncthreads();

    float e = (tid < S_) ? __expf(v - m) : 0.f;
    float su = e;
    #pragma unroll
    for (int o = 16; o; o >>= 1) su += __shfl_xor_sync(0xffffffffu, su, o);
    if (lane == 0) red[warp] = su;
    __syncthreads();
    if (tid == 0) {
        float ss = 0.f;
        #pragma unroll
        for (int i = 0; i < 8; i++) ss += red[i];
        red[0] = ss;
    }
    __syncthreads();
    const float inv = 1.0f / red[0];
    if (tid < S_) {
        float wnorm = e * inv;
        ws[tid] = wnorm;
        if (rc == 0) weight_out[b * S_ + tid] = wnorm;
    }
    __syncthreads();

    // --- direct pooling: this thread's r column, all 196 s ---
    const int r = rc * 256 + tid;
    const float* af = att_feats + (size_t)b * S_ * R_ + r;
    float acc = 0.f;
    #pragma unroll 7
    for (int s = 0; s < S_; s++) {
        acc = fmaf(ws[s], af[(size_t)s * R_], acc);
    }
    att_res[(size_t)b * R_ + r] = acc;
}

// ---------------------------------------------------------------------------
extern "C" void kernel_launch(void* const* d_in, const int* in_sizes, int n_in,
                              void* d_out, int out_size) {
    const float* att_feats = (const float*)d_in[0];  // [B,S,R]
    const float* p_att     = (const float*)d_in[1];  // [B,S,H]
    const float* hidden    = (const float*)d_in[2];  // [B,R]
    const float* in_w      = (const float*)d_in[3];  // [B,S]
    const float* h2w       = (const float*)d_in[4];  // [H,R]
    const float* h2b       = (const float*)d_in[5];  // [H]
    const float* aw        = (const float*)d_in[6];  // [1,H]
    const float* ab        = (const float*)d_in[7];  // [1]

    float* out     = (float*)d_out;
    float* att_res = out;                 // [B,R]
    float* weight  = out + B_ * R_;       // [B,S]

    // Kernel A: normal launch
    k_h2att<<<dim3(H_ / BN, B_ / BM, KSPLIT), 256>>>(hidden, h2w, h2b);

    // Kernel B: PDL — may launch while A drains; syncs internally.
    {
        cudaLaunchConfig_t cfg = {};
        cfg.gridDim = dim3(2, B_);
        cfg.blockDim = dim3(512);
        cfg.stream = 0;
        cudaLaunchAttribute attr[1];
        attr[0].id = cudaLaunchAttributeProgrammaticStreamSerialization;
        attr[0].val.programmaticStreamSerializationAllowed = 1;
        cfg.attrs = attr;
        cfg.numAttrs = 1;
        cudaLaunchKernelEx(&cfg, k_scores, p_att, in_w, aw, ab);
    }

    // Kernel C: PDL — may launch while B drains; syncs internally.
    {
        cudaLaunchConfig_t cfg = {};
        cfg.gridDim = dim3(4, B_);
        cfg.blockDim = dim3(256);
        cfg.stream = 0;
        cudaLaunchAttribute attr[1];
        attr[0].id = cudaLaunchAttributeProgrammaticStreamSerialization;
        attr[0].val.programmaticStreamSerializationAllowed = 1;
        cfg.attrs = attr;
        cfg.numAttrs = 1;
        cudaLaunchKernelEx(&cfg, k_pool, att_feats, weight, att_res);
    }
}

// round 16
// speedup vs baseline: 1.1569x; 1.0645x over previous
#include <cuda_runtime.h>

#define B_ 256
#define S_ 196
#define R_ 1024
#define H_ 512

#define KSPLIT 16
#define KCHUNK (R_ / KSPLIT)     // 64

// GEMM tiling for k_h2att: 128x128 CTA tile, 8x8 micro-tile, BK=8
#define BM 128
#define BN 128
#define BK 8
#define NTILES (KCHUNK / BK)     // 8

// Scratch (no allocations allowed anywhere)
__device__ float g_att_h_part[KSPLIT * B_ * H_];
__device__ float g_scores[B_ * S_];

__device__ __forceinline__ float tanh_fast(float x) {
    float y;
    asm("tanh.approx.f32 %0, %1;" : "=f"(y) : "f"(x));
    return y;
}

// ---------------------------------------------------------------------------
// Kernel A: partial att_h = hidden @ W^T (+bias on z==0 split).
// grid (H/BN=4, B/BM=2, KSPLIT=16) = 128 blocks, 256 threads.
// 8x8 micro-tile: per kk, 4x LDS.128 feed 64 FMA (a-frags broadcast).
// Ping-pong smem + register staging, one sync per k-tile.
// ---------------------------------------------------------------------------
__global__ void __launch_bounds__(256)
k_h2att(const float* __restrict__ hidden,
        const float* __restrict__ W,
        const float* __restrict__ bias) {
    __shared__ __align__(16) float As[2][BK][BM + 4];   // [buf][kk][b-row]
    __shared__ __align__(16) float Bs[2][BK][BN + 4];   // [buf][kk][h-col]
    const int h0 = blockIdx.x * BN;
    const int b0 = blockIdx.y * BM;
    const int z  = blockIdx.z;
    const int tid = threadIdx.x;

    const int srow = tid >> 1;            // 0..127 (row to stage)
    const int sk   = (tid & 1) * 4;       // 0 or 4 (k quad)

    const int tx8 = (tid & 15) * 8;       // h micro col base
    const int ty8 = (tid >> 4) * 8;       // b micro row base

    float acc[8][8] = {};

    const int kbeg = z * KCHUNK;
    const float* ha = &hidden[(size_t)(b0 + srow) * R_ + kbeg + sk];
    const float* wa = &W[(size_t)(h0 + srow) * R_ + kbeg + sk];

    // prologue: stage tile 0 into buffer 0
    {
        float4 av = *(const float4*)ha;
        float4 bv = *(const float4*)wa;
        As[0][sk + 0][srow] = av.x;
        As[0][sk + 1][srow] = av.y;
        As[0][sk + 2][srow] = av.z;
        As[0][sk + 3][srow] = av.w;
        Bs[0][sk + 0][srow] = bv.x;
        Bs[0][sk + 1][srow] = bv.y;
        Bs[0][sk + 2][srow] = bv.z;
        Bs[0][sk + 3][srow] = bv.w;
    }
    __syncthreads();

    #pragma unroll
    for (int i = 0; i < NTILES; i++) {
        float4 av, bv;
        if (i + 1 < NTILES) {              // issue next tile's loads early
            av = *(const float4*)(ha + (i + 1) * BK);
            bv = *(const float4*)(wa + (i + 1) * BK);
        }

        const int p = i & 1;
        #pragma unroll
        for (int kk = 0; kk < BK; kk++) {
            float4 a0 = *(const float4*)&As[p][kk][ty8];
            float4 a1 = *(const float4*)&As[p][kk][ty8 + 4];
            float4 bb0 = *(const float4*)&Bs[p][kk][tx8];
            float4 bb1 = *(const float4*)&Bs[p][kk][tx8 + 4];
            float ar[8] = {a0.x, a0.y, a0.z, a0.w, a1.x, a1.y, a1.z, a1.w};
            float br[8] = {bb0.x, bb0.y, bb0.z, bb0.w, bb1.x, bb1.y, bb1.z, bb1.w};
            #pragma unroll
            for (int r = 0; r < 8; r++)
                #pragma unroll
                for (int cclk = 0; cclk < 8; cclk++)
                    acc[r][cclk] = fmaf(ar[r], br[cclk], acc[r][cclk]);
        }

        if (i + 1 < NTILES) {
            const int q = (i + 1) & 1;
            As[q][sk + 0][srow] = av.x;
            As[q][sk + 1][srow] = av.y;
            As[q][sk + 2][srow] = av.z;
            As[q][sk + 3][srow] = av.w;
            Bs[q][sk + 0][srow] = bv.x;
            Bs[q][sk + 1][srow] = bv.y;
            Bs[q][sk + 2][srow] = bv.z;
            Bs[q][sk + 3][srow] = bv.w;
            __syncthreads();
        }
    }

    float bb[8] = {};
    if (z == 0) {
        float4 b0v = *(const float4*)&bias[h0 + tx8];
        float4 b1v = *(const float4*)&bias[h0 + tx8 + 4];
        bb[0] = b0v.x; bb[1] = b0v.y; bb[2] = b0v.z; bb[3] = b0v.w;
        bb[4] = b1v.x; bb[5] = b1v.y; bb[6] = b1v.z; bb[7] = b1v.w;
    }

    float* outp = g_att_h_part + (size_t)z * B_ * H_;
    #pragma unroll
    for (int r = 0; r < 8; r++) {
        float4 r0 = make_float4(acc[r][0] + bb[0], acc[r][1] + bb[1],
                                acc[r][2] + bb[2], acc[r][3] + bb[3]);
        float4 r1 = make_float4(acc[r][4] + bb[4], acc[r][5] + bb[5],
                                acc[r][6] + bb[6], acc[r][7] + bb[7]);
        *(float4*)&outp[(size_t)(b0 + ty8 + r) * H_ + h0 + tx8]     = r0;
        *(float4*)&outp[(size_t)(b0 + ty8 + r) * H_ + h0 + tx8 + 4] = r1;
    }
}

// ---------------------------------------------------------------------------
// Kernel B: scores. grid (2, B), 512 threads (16 warps).
// Each block: one b, half of S (98 rows). att_h partials reduced once into smem.
// ---------------------------------------------------------------------------
__global__ void __launch_bounds__(512)
k_scores(const float* __restrict__ p_att,
         const float* __restrict__ in_w,
         const float* __restrict__ alpha_w,
         const float* __restrict__ alpha_b) {
    __shared__ __align__(16) float sh_ah[H_];
    __shared__ __align__(16) float sh_al[H_];
    const int b = blockIdx.y;
    const int c = blockIdx.x;          // 0 or 1 (half of S)
    const int tid = threadIdx.x;

    if (tid < H_) {
        size_t o = (size_t)b * H_ + tid;
        float v = 0.f;
        #pragma unroll
        for (int p = 0; p < KSPLIT; p++)
            v += g_att_h_part[(size_t)p * B_ * H_ + o];
        sh_ah[tid] = v;
        sh_al[tid] = alpha_w[tid];
    }
    __syncthreads();

    const int warp = tid >> 5, lane = tid & 31;
    const float4* ah4 = (const float4*)sh_ah;
    const float4* al4 = (const float4*)sh_al;
    const float ab0 = alpha_b[0];

    for (int sl = warp; sl < S_ / 2; sl += 16) {
        const int s = c * (S_ / 2) + sl;
        const float iw = in_w[b * S_ + s];
        const float4* p4 = (const float4*)(p_att + ((size_t)b * S_ + s) * H_);
        float acc = 0.f;
        #pragma unroll
        for (int j = 0; j < 4; j++) {
            float4 p = p4[j * 32 + lane];
            float4 a = ah4[j * 32 + lane];
            float4 w = al4[j * 32 + lane];
            acc += tanh_fast(fmaf(iw, p.x, a.x)) * w.x;
            acc += tanh_fast(fmaf(iw, p.y, a.y)) * w.y;
            acc += tanh_fast(fmaf(iw, p.z, a.z)) * w.z;
            acc += tanh_fast(fmaf(iw, p.w, a.w)) * w.w;
        }
        #pragma unroll
        for (int o = 16; o; o >>= 1)
            acc += __shfl_xor_sync(0xffffffffu, acc, o);
        if (lane == 0)
            g_scores[b * S_ + s] = acc + ab0;
    }
}

// ---------------------------------------------------------------------------
// Kernel C: fused softmax + direct pooling. grid (4, B), 256 threads.
// Softmax recomputed per block (deterministic, identical order); rc==0 writes
// weight. Each thread owns one scalar r column over all 196 s.
// ---------------------------------------------------------------------------
__global__ void __launch_bounds__(256)
k_pool(const float* __restrict__ att_feats,
       float* __restrict__ weight_out,
       float* __restrict__ att_res) {
    __shared__ float ws[S_];
    __shared__ float red[8];
    const int b  = blockIdx.y;
    const int rc = blockIdx.x;         // r chunk 0..3
    const int tid = threadIdx.x;
    const int warp = tid >> 5, lane = tid & 31;

    // --- softmax over S (256 threads, one score each) ---
    float v = (tid < S_) ? g_scores[b * S_ + tid] : -1e30f;
    float m = v;
    #pragma unroll
    for (int o = 16; o; o >>= 1) m = fmaxf(m, __shfl_xor_sync(0xffffffffu, m, o));
    if (lane == 0) red[warp] = m;
    __syncthreads();
    if (tid == 0) {
        float mm = red[0];
        #pragma unroll
        for (int i = 1; i < 8; i++) mm = fmaxf(mm, red[i]);
        red[0] = mm;
    }
    __syncthreads();
    m = red[0];
    __syncthreads();

    float e = (tid < S_) ? __expf(v - m) : 0.f;
    float su = e;
    #pragma unroll
    for (int o = 16; o; o >>= 1) su += __shfl_xor_sync(0xffffffffu, su, o);
    if (lane == 0) red[warp] = su;
    __syncthreads();
    if (tid == 0) {
        float ss = 0.f;
        #pragma unroll
        for (int i = 0; i < 8; i++) ss += red[i];
        red[0] = ss;
    }
    __syncthreads();
    const float inv = 1.0f / red[0];
    if (tid < S_) {
        float wnorm = e * inv;
        ws[tid] = wnorm;
        if (rc == 0) weight_out[b * S_ + tid] = wnorm;
    }
    __syncthreads();

    // --- direct pooling: this thread's r column, all 196 s ---
    const int r = rc * 256 + tid;
    const float* af = att_feats + (size_t)b * S_ * R_ + r;
    float acc = 0.f;
    #pragma unroll 7
    for (int s = 0; s < S_; s++) {
        acc = fmaf(ws[s], af[(size_t)s * R_], acc);
    }
    att_res[(size_t)b * R_ + r] = acc;
}

// ---------------------------------------------------------------------------
extern "C" void kernel_launch(void* const* d_in, const int* in_sizes, int n_in,
                              void* d_out, int out_size) {
    const float* att_feats = (const float*)d_in[0];  // [B,S,R]
    const float* p_att     = (const float*)d_in[1];  // [B,S,H]
    const float* hidden    = (const float*)d_in[2];  // [B,R]
    const float* in_w      = (const float*)d_in[3];  // [B,S]
    const float* h2w       = (const float*)d_in[4];  // [H,R]
    const float* h2b       = (const float*)d_in[5];  // [H]
    const float* aw        = (const float*)d_in[6];  // [1,H]
    const float* ab        = (const float*)d_in[7];  // [1]

    float* out     = (float*)d_out;
    float* att_res = out;                 // [B,R]
    float* weight  = out + B_ * R_;       // [B,S]

    k_h2att <<<dim3(H_ / BN, B_ / BM, KSPLIT), 256>>>(hidden, h2w, h2b);
    k_scores<<<dim3(2, B_), 512>>>(p_att, in_w, aw, ab);
    k_pool  <<<dim3(4, B_), 256>>>(att_feats, weight, att_res);
}